// round 5
// baseline (speedup 1.0000x reference)
#include <cuda_runtime.h>
#include <math.h>
#include <stdint.h>

#define LSEQ 1026
#define BB   2
#define BLT  (BB*LSEQ)   // 2052
#define DMO  256
#define EDI  512
#define ED2  1024
#define NS   16
#define RRW  16
#define DBCW 48
#define NBR  4
#define NCHK 18
#define CLEN 57          // 18*57 = 1026
#define EHALF 256

// ------------------------- scratch (device globals; no allocs) -------------
__device__ float g_xz[(size_t)BLT*ED2];
__device__ float g_xa[NBR][(size_t)BLT*EDI];
__device__ float g_dbc[NBR][(size_t)BLT*DBCW];
__device__ float g_sum[(size_t)NBR*BB*NCHK*32*EDI];
__device__ float g_h0[(size_t)NBR*BB*NCHK*NS*EDI];
__device__ float g_g[NBR][(size_t)BLT*EDI];
__device__ int   g_fast[NBR];

struct BranchPtrs { const float *cw,*cb,*xpw,*dtw,*dtb,*Al,*Dp; };
struct AllPtrs { BranchPtrs br[NBR]; };

// ------------------------- index maps ---------------------------------------
__device__ __forceinline__ int pi_map(int p) {
    if (p == 0 || p == LSEQ - 1) return p;
    int q = p - 1;
    int i = q >> 5, j = q & 31;
    return (j << 5) + i + 1;
}
__device__ __forceinline__ int in_row(int s, int p) {
    if (s == 0) return p;
    if (s == 1) return LSEQ - 1 - p;
    if (s == 2) return pi_map(p);
    return pi_map(LSEQ - 1 - p);
}

#define STORE_A8(ARR, KQ, R, V0, V1) \
    ARR[(KQ)+0][R]=(V0).x; ARR[(KQ)+1][R]=(V0).y; ARR[(KQ)+2][R]=(V0).z; ARR[(KQ)+3][R]=(V0).w; \
    ARR[(KQ)+4][R]=(V1).x; ARR[(KQ)+5][R]=(V1).y; ARR[(KQ)+6][R]=(V1).z; ARR[(KQ)+7][R]=(V1).w;

// ===== in-GEMM: xz = x @ in_w^T, 128x128x64 staged, split-K(4), atomic ======
__global__ __launch_bounds__(256)
void in_gemm_staged(const float* __restrict__ A, const float* __restrict__ Bm,
                    float* __restrict__ C) {
    extern __shared__ float sh[];
    float (*As)[128] = (float(*)[128])sh;
    float (*Bs)[128] = (float(*)[128])(sh + 64 * 128);
    int tid = threadIdx.x, tx = tid & 15, ty = tid >> 4;
    int n0 = blockIdx.x * 128, m0 = blockIdx.y * 128, kbase = blockIdx.z * 64;
    int r = tid >> 1, kq = (tid & 1) * 8;
    bool mok = (m0 + r) < BLT;
    const float* Ap = A + (size_t)(m0 + r) * DMO + kbase + kq;
    const float* Bp = Bm + (size_t)(n0 + r) * DMO + kbase + kq;
    float4 av[8], bv[8];
#pragma unroll
    for (int i = 0; i < 4; i++) {
        if (mok) { av[2*i] = *(const float4*)(Ap + 16*i); av[2*i+1] = *(const float4*)(Ap + 16*i + 4); }
        else     { av[2*i] = make_float4(0,0,0,0); av[2*i+1] = av[2*i]; }
    }
#pragma unroll
    for (int i = 0; i < 4; i++) {
        bv[2*i] = *(const float4*)(Bp + 16*i); bv[2*i+1] = *(const float4*)(Bp + 16*i + 4);
    }
#pragma unroll
    for (int i = 0; i < 4; i++) {
        int k0 = kq + 16 * i;
        STORE_A8(As, k0, r, av[2*i], av[2*i+1]);
        STORE_A8(Bs, k0, r, bv[2*i], bv[2*i+1]);
    }
    __syncthreads();

    float acc[8][8];
#pragma unroll
    for (int i = 0; i < 8; i++)
#pragma unroll
        for (int j = 0; j < 8; j++) acc[i][j] = 0.f;

#pragma unroll 1
    for (int c = 0; c < 4; c++) {
#pragma unroll
        for (int k16 = 0; k16 < 16; k16++) {
            int k = c * 16 + k16;
            float4 av0 = *(float4*)&As[k][ty*4];
            float4 av1 = *(float4*)&As[k][64 + ty*4];
            float4 bv0 = *(float4*)&Bs[k][tx*4];
            float4 bv1 = *(float4*)&Bs[k][64 + tx*4];
            float a4[8] = {av0.x,av0.y,av0.z,av0.w, av1.x,av1.y,av1.z,av1.w};
            float b4[8] = {bv0.x,bv0.y,bv0.z,bv0.w, bv1.x,bv1.y,bv1.z,bv1.w};
#pragma unroll
            for (int i = 0; i < 8; i++)
#pragma unroll
                for (int j = 0; j < 8; j++)
                    acc[i][j] = fmaf(a4[i], b4[j], acc[i][j]);
        }
    }
#pragma unroll
    for (int i = 0; i < 8; i++) {
        int m = m0 + (i >> 2) * 64 + ty * 4 + (i & 3);
        if (m >= BLT) continue;
#pragma unroll
        for (int j = 0; j < 8; j++) {
            int n = n0 + (j >> 2) * 64 + tx * 4 + (j & 3);
            atomicAdd(&C[(size_t)m * ED2 + n], acc[i][j]);
        }
    }
}

// ===== dBC: 128x48x64 staged, batched branches, split-K(8), atomic ==========
__global__ __launch_bounds__(256)
void dbc_staged(AllPtrs P) {
    __shared__ float As[64][128];
    __shared__ float Bs[64][48];
    int tid = threadIdx.x, tx = tid & 15, ty = tid >> 4;
    int m0 = blockIdx.y * 128;
    int s = blockIdx.z >> 3, kz = blockIdx.z & 7;
    int kbase = kz * 64;
    const float* A  = g_xa[s];
    const float* Bm = P.br[s].xpw;
    float*       C  = g_dbc[s];
    int r = tid >> 1, kq = (tid & 1) * 8;
    bool mok = (m0 + r) < BLT;
    const float* Ap = A + (size_t)(m0 + r) * EDI + kbase + kq;
    float4 av[8];
#pragma unroll
    for (int i = 0; i < 4; i++) {
        if (mok) { av[2*i] = *(const float4*)(Ap + 16*i); av[2*i+1] = *(const float4*)(Ap + 16*i + 4); }
        else     { av[2*i] = make_float4(0,0,0,0); av[2*i+1] = av[2*i]; }
    }
    bool bok = tid < 192;
    int brow = tid >> 2, bkq = (tid & 3) * 4;
    const float* Bp = Bm + (size_t)brow * EDI + kbase + bkq;
    float4 bv[4];
#pragma unroll
    for (int i = 0; i < 4; i++)
        bv[i] = bok ? *(const float4*)(Bp + 16*i) : make_float4(0,0,0,0);
#pragma unroll
    for (int i = 0; i < 4; i++) {
        int k0 = kq + 16 * i;
        STORE_A8(As, k0, r, av[2*i], av[2*i+1]);
    }
    if (bok) {
#pragma unroll
        for (int i = 0; i < 4; i++) {
            int k0 = bkq + 16 * i;
            Bs[k0+0][brow]=bv[i].x; Bs[k0+1][brow]=bv[i].y;
            Bs[k0+2][brow]=bv[i].z; Bs[k0+3][brow]=bv[i].w;
        }
    }
    __syncthreads();

    float acc[8][3];
#pragma unroll
    for (int i = 0; i < 8; i++)
#pragma unroll
        for (int j = 0; j < 3; j++) acc[i][j] = 0.f;

#pragma unroll 1
    for (int c = 0; c < 4; c++) {
#pragma unroll
        for (int k16 = 0; k16 < 16; k16++) {
            int k = c * 16 + k16;
            float4 av0 = *(float4*)&As[k][ty*4];
            float4 av1 = *(float4*)&As[k][64 + ty*4];
            float a4[8] = {av0.x,av0.y,av0.z,av0.w, av1.x,av1.y,av1.z,av1.w};
            float b4[3] = {Bs[k][tx*3], Bs[k][tx*3+1], Bs[k][tx*3+2]};
#pragma unroll
            for (int i = 0; i < 8; i++)
#pragma unroll
                for (int j = 0; j < 3; j++)
                    acc[i][j] = fmaf(a4[i], b4[j], acc[i][j]);
        }
    }
#pragma unroll
    for (int i = 0; i < 8; i++) {
        int m = m0 + (i >> 2) * 64 + ty * 4 + (i & 3);
        if (m >= BLT) continue;
#pragma unroll
        for (int j = 0; j < 3; j++)
            atomicAdd(&C[(size_t)m * DBCW + tx * 3 + j], acc[i][j]);
    }
}

// ===== out-GEMM fused combine-gather, 128x128x64 staged, split-K(8) =========
__global__ __launch_bounds__(256)
void out_gemm_staged(const float* __restrict__ out_w, float* __restrict__ C) {
    extern __shared__ float sh[];
    float (*As)[128] = (float(*)[128])sh;
    float (*Bs)[128] = (float(*)[128])(sh + 64 * 128);
    int tid = threadIdx.x, tx = tid & 15, ty = tid >> 4;
    int n0 = blockIdx.x * 128, m0 = blockIdx.y * 128, kbase = blockIdx.z * 64;
    int r = tid >> 1, kq = (tid & 1) * 8;
    int m = m0 + r;
    bool mok = m < BLT;
    size_t r0 = 0, r1 = 0, r2 = 0, r3 = 0;
    if (mok) {
        int b = m / LSEQ, l = m % LSEQ;
        r0 = (size_t)m * EDI;
        r1 = (size_t)(b * LSEQ + (LSEQ - 1 - l)) * EDI;
        r2 = (size_t)(b * LSEQ + pi_map(l)) * EDI;
        r3 = (size_t)(b * LSEQ + pi_map(LSEQ - 1 - l)) * EDI;
    }
    float4 av[8], bv[8];
#pragma unroll
    for (int i = 0; i < 4; i++) {
        av[2*i] = make_float4(0,0,0,0); av[2*i+1] = av[2*i];
        if (mok) {
            int kk = kbase + kq + 16 * i;
            float4 p0 = *(const float4*)(g_g[0]+r0+kk), p1 = *(const float4*)(g_g[1]+r1+kk);
            float4 p2 = *(const float4*)(g_g[2]+r2+kk), p3 = *(const float4*)(g_g[3]+r3+kk);
            float4 q0 = *(const float4*)(g_g[0]+r0+kk+4), q1 = *(const float4*)(g_g[1]+r1+kk+4);
            float4 q2 = *(const float4*)(g_g[2]+r2+kk+4), q3 = *(const float4*)(g_g[3]+r3+kk+4);
            av[2*i].x = 0.25f*(p0.x+p1.x+p2.x+p3.x); av[2*i].y = 0.25f*(p0.y+p1.y+p2.y+p3.y);
            av[2*i].z = 0.25f*(p0.z+p1.z+p2.z+p3.z); av[2*i].w = 0.25f*(p0.w+p1.w+p2.w+p3.w);
            av[2*i+1].x = 0.25f*(q0.x+q1.x+q2.x+q3.x); av[2*i+1].y = 0.25f*(q0.y+q1.y+q2.y+q3.y);
            av[2*i+1].z = 0.25f*(q0.z+q1.z+q2.z+q3.z); av[2*i+1].w = 0.25f*(q0.w+q1.w+q2.w+q3.w);
        }
    }
    const float* Bp = out_w + (size_t)(n0 + r) * EDI + kbase + kq;
#pragma unroll
    for (int i = 0; i < 4; i++) {
        bv[2*i] = *(const float4*)(Bp + 16*i); bv[2*i+1] = *(const float4*)(Bp + 16*i + 4);
    }
#pragma unroll
    for (int i = 0; i < 4; i++) {
        int k0 = kq + 16 * i;
        STORE_A8(As, k0, r, av[2*i], av[2*i+1]);
        STORE_A8(Bs, k0, r, bv[2*i], bv[2*i+1]);
    }
    __syncthreads();

    float acc[8][8];
#pragma unroll
    for (int i = 0; i < 8; i++)
#pragma unroll
        for (int j = 0; j < 8; j++) acc[i][j] = 0.f;

#pragma unroll 1
    for (int c = 0; c < 4; c++) {
#pragma unroll
        for (int k16 = 0; k16 < 16; k16++) {
            int k = c * 16 + k16;
            float4 av0 = *(float4*)&As[k][ty*4];
            float4 av1 = *(float4*)&As[k][64 + ty*4];
            float4 bv0 = *(float4*)&Bs[k][tx*4];
            float4 bv1 = *(float4*)&Bs[k][64 + tx*4];
            float a4[8] = {av0.x,av0.y,av0.z,av0.w, av1.x,av1.y,av1.z,av1.w};
            float b4[8] = {bv0.x,bv0.y,bv0.z,bv0.w, bv1.x,bv1.y,bv1.z,bv1.w};
#pragma unroll
            for (int i = 0; i < 8; i++)
#pragma unroll
                for (int j = 0; j < 8; j++)
                    acc[i][j] = fmaf(a4[i], b4[j], acc[i][j]);
        }
    }
#pragma unroll
    for (int i = 0; i < 8; i++) {
        int mm = m0 + (i >> 2) * 64 + ty * 4 + (i & 3);
        if (mm >= BLT) continue;
#pragma unroll
        for (int j = 0; j < 8; j++) {
            int n = n0 + (j >> 2) * 64 + tx * 4 + (j & 3);
            atomicAdd(&C[(size_t)mm * DMO + n], acc[i][j]);
        }
    }
}

// ------------------------- structure check for A = -(n+1) -------------------
__global__ void flag_kernel(AllPtrs P) {
    __shared__ int ok;
    int s = blockIdx.x;
    if (threadIdx.x == 0) ok = 1;
    __syncthreads();
    const float* Al = P.br[s].Al;
    int e = threadIdx.x;
    bool good = true;
#pragma unroll
    for (int n = 0; n < NS; n++) {
        float ref = logf((float)(n + 1));
        if (fabsf(Al[e * NS + n] - ref) > 1e-5f * fmaxf(1.f, fabsf(ref))) good = false;
    }
    if (!good) atomicAnd(&ok, 0);
    __syncthreads();
    if (threadIdx.x == 0) g_fast[s] = ok;
}

// ------- depthwise conv (K=4 causal) + SiLU, rolling window over 6 pos ------
#define CONV_T 6
__global__ __launch_bounds__(512)
void conv_silu(AllPtrs P) {
    int blk = blockIdx.x;
    int ntile = LSEQ / CONV_T;           // 171
    int s  = blk / (BB * ntile);
    int rm = blk % (BB * ntile);
    int b  = rm / ntile;
    int l0 = (rm % ntile) * CONV_T;
    int e  = threadIdx.x;
    float4 cwv = *(const float4*)(P.br[s].cw + e * 4);
    float cb = P.br[s].cb[e];
    float v0 = 0.f, v1 = 0.f, v2 = 0.f;
    if (l0 - 3 >= 0) v0 = g_xz[(size_t)(b * LSEQ + in_row(s, l0 - 3)) * ED2 + e];
    if (l0 - 2 >= 0) v1 = g_xz[(size_t)(b * LSEQ + in_row(s, l0 - 2)) * ED2 + e];
    if (l0 - 1 >= 0) v2 = g_xz[(size_t)(b * LSEQ + in_row(s, l0 - 1)) * ED2 + e];
#pragma unroll
    for (int t = 0; t < CONV_T; t++) {
        int l = l0 + t;
        float v3 = g_xz[(size_t)(b * LSEQ + in_row(s, l)) * ED2 + e];
        float acc = cb;
        acc = fmaf(cwv.x, v0, acc);
        acc = fmaf(cwv.y, v1, acc);
        acc = fmaf(cwv.z, v2, acc);
        acc = fmaf(cwv.w, v3, acc);
        float sg = 1.f / (1.f + __expf(-acc));
        g_xa[s][(size_t)(b * LSEQ + l) * EDI + e] = acc * sg;
        v0 = v1; v1 = v2; v2 = v3;
    }
}

// -------- scan phase 1: chunk summaries, delta fused, channel-split ---------
__global__ __launch_bounds__(256)
void scan1(AllPtrs P) {
    __shared__ float dtw_s[EHALF * 17];
    __shared__ float f_s[CLEN][NS];
    __shared__ float Bsm[CLEN * NS];
    int blk = blockIdx.x;
    int half = blk & 1;
    int blk2 = blk >> 1;
    int s = blk2 / (BB * NCHK);
    int rem = blk2 % (BB * NCHK);
    int b = rem / NCHK, c = rem % NCHK;
    int e0 = half * EHALF;
    int e = e0 + threadIdx.x;
    const float* dtw = P.br[s].dtw;
    for (int idx = threadIdx.x; idx < EHALF * RRW; idx += blockDim.x)
        dtw_s[(idx >> 4) * 17 + (idx & 15)] = dtw[e0 * RRW + idx];
    for (int idx = threadIdx.x; idx < CLEN * 32; idx += blockDim.x) {
        int t = idx >> 5, q = idx & 31;
        float v = g_dbc[s][(size_t)(b * LSEQ + c * CLEN + t) * DBCW + q];
        if (q < 16) f_s[t][q] = v;
        else        Bsm[t * NS + (q - 16)] = v;
    }
    __syncthreads();
    float w[RRW];
#pragma unroll
    for (int q = 0; q < RRW; q++) w[q] = dtw_s[threadIdx.x * 17 + q];
    float dtb = P.br[s].dtb[e];
    int fast = g_fast[s];
    float A_[NS];
    if (!fast) {
        const float* Al = P.br[s].Al;
#pragma unroll
        for (int n = 0; n < NS; n++) A_[n] = -__expf(Al[e * NS + n]);
    }
    float h[NS], Pn[NS];
#pragma unroll
    for (int n = 0; n < NS; n++) { h[n] = 0.f; Pn[n] = 1.f; }
    float Rp = 1.f;
    const float* xptr = g_xa[s] + (size_t)(b * LSEQ + c * CLEN) * EDI + e;
    float x_cur = xptr[0];
    for (int t = 0; t < CLEN; t++) {
        float x_nxt = (t + 1 < CLEN) ? xptr[(size_t)(t + 1) * EDI] : 0.f;
        float u = dtb;
#pragma unroll
        for (int q = 0; q < RRW; q++) u = fmaf(f_s[t][q], w[q], u);
        float d = fmaxf(u, 0.f) + log1pf(__expf(-fabsf(u)));
        float dx = d * x_cur;
        if (fast) {
            float r = __expf(-d);
            Rp *= r;
            float dA = 1.f;
#pragma unroll
            for (int n = 0; n < NS; n++) {
                dA *= r;
                h[n] = fmaf(dA, h[n], dx * Bsm[t * NS + n]);
            }
        } else {
#pragma unroll
            for (int n = 0; n < NS; n++) {
                float dA = __expf(d * A_[n]);
                Pn[n] *= dA;
                h[n] = fmaf(dA, h[n], dx * Bsm[t * NS + n]);
            }
        }
        x_cur = x_nxt;
    }
    if (fast) {
        float q = 1.f;
#pragma unroll
        for (int n = 0; n < NS; n++) { q *= Rp; Pn[n] = q; }
    }
    size_t base = (size_t)((s * BB + b) * NCHK + c) * 32 * EDI + e;
#pragma unroll
    for (int n = 0; n < NS; n++) g_sum[base + (size_t)n * EDI] = h[n];
#pragma unroll
    for (int n = 0; n < NS; n++) g_sum[base + (size_t)(16 + n) * EDI] = Pn[n];
}

// ---------- scan phase 2: chunk combine, parallel over (s,b,n) --------------
__global__ __launch_bounds__(512)
void scan2() {
    int n = blockIdx.x & 15;
    int sb = blockIdx.x >> 4;          // s*BB+b
    int e = threadIdx.x;
    float h = 0.f;
    for (int c = 0; c < NCHK; c++) {
        size_t idx = (size_t)(sb * NCHK + c);
        g_h0[idx * NS * EDI + (size_t)n * EDI + e] = h;
        size_t pb = idx * 32 * EDI + e;
        float hl = g_sum[pb + (size_t)n * EDI];
        float Pv = g_sum[pb + (size_t)(16 + n) * EDI];
        h = fmaf(Pv, h, hl);
    }
}

// -------- scan phase 3: full walk + gate, delta fused, channel-split --------
__global__ __launch_bounds__(256)
void scan3(AllPtrs P) {
    __shared__ float dtw_s[EHALF * 17];
    __shared__ float f_s[CLEN][NS];
    __shared__ float Bsm[CLEN * NS];
    __shared__ float Csm[CLEN * NS];
    int blk = blockIdx.x;
    int half = blk & 1;
    int blk2 = blk >> 1;
    int s = blk2 / (BB * NCHK);
    int rem = blk2 % (BB * NCHK);
    int b = rem / NCHK, c = rem % NCHK;
    int e0 = half * EHALF;
    int e = e0 + threadIdx.x;
    const float* dtw = P.br[s].dtw;
    for (int idx = threadIdx.x; idx < EHALF * RRW; idx += blockDim.x)
        dtw_s[(idx >> 4) * 17 + (idx & 15)] = dtw[e0 * RRW + idx];
    for (int idx = threadIdx.x; idx < CLEN * DBCW; idx += blockDim.x) {
        int t = idx / DBCW, q = idx % DBCW;
        float v = g_dbc[s][(size_t)(b * LSEQ + c * CLEN + t) * DBCW + q];
        if (q < 16)      f_s[t][q] = v;
        else if (q < 32) Bsm[t * NS + (q - 16)] = v;
        else             Csm[t * NS + (q - 32)] = v;
    }
    __syncthreads();
    float w[RRW];
#pragma unroll
    for (int q = 0; q < RRW; q++) w[q] = dtw_s[threadIdx.x * 17 + q];
    float dtb = P.br[s].dtb[e];
    int fast = g_fast[s];
    float A_[NS];
    if (!fast) {
        const float* Al = P.br[s].Al;
#pragma unroll
        for (int n = 0; n < NS; n++) A_[n] = -__expf(Al[e * NS + n]);
    }
    float Dv = P.br[s].Dp[e];
    float h[NS];
    {
        size_t sb = (size_t)((s * BB + b) * NCHK + c);
        size_t hb = sb * NS * EDI + e;
#pragma unroll
        for (int n = 0; n < NS; n++) h[n] = g_h0[hb + (size_t)n * EDI];
    }
    const float* xptr = g_xa[s] + (size_t)(b * LSEQ + c * CLEN) * EDI + e;
    float x_cur = xptr[0];
    float za_cur = g_xz[(size_t)(b * LSEQ + in_row(s, c * CLEN)) * ED2 + EDI + e];
    for (int t = 0; t < CLEN; t++) {
        int l = c * CLEN + t;
        int bl = b * LSEQ + l;
        float x_nxt = 0.f, za_nxt = 0.f;
        if (t + 1 < CLEN) {
            x_nxt = xptr[(size_t)(t + 1) * EDI];
            za_nxt = g_xz[(size_t)(b * LSEQ + in_row(s, l + 1)) * ED2 + EDI + e];
        }
        float u = dtb;
#pragma unroll
        for (int q = 0; q < RRW; q++) u = fmaf(f_s[t][q], w[q], u);
        float d = fmaxf(u, 0.f) + log1pf(__expf(-fabsf(u)));
        float dx = d * x_cur;
        float acc = Dv * x_cur;
        if (fast) {
            float r = __expf(-d);
            float dA = 1.f;
#pragma unroll
            for (int n = 0; n < NS; n++) {
                dA *= r;
                h[n] = fmaf(dA, h[n], dx * Bsm[t * NS + n]);
                acc = fmaf(h[n], Csm[t * NS + n], acc);
            }
        } else {
#pragma unroll
            for (int n = 0; n < NS; n++) {
                float dA = __expf(d * A_[n]);
                h[n] = fmaf(dA, h[n], dx * Bsm[t * NS + n]);
                acc = fmaf(h[n], Csm[t * NS + n], acc);
            }
        }
        float sz = za_cur / (1.f + __expf(-za_cur));
        g_g[s][(size_t)bl * EDI + e] = acc * sz;
        x_cur = x_nxt; za_cur = za_nxt;
    }
}

// ------------------------- launch ------------------------------------------
extern "C" void kernel_launch(void* const* d_in, const int* in_sizes, int n_in,
                              void* d_out, int out_size) {
    const float* x     = (const float*)d_in[0];
    const float* in_w  = (const float*)d_in[1];
    const float* out_w = (const float*)d_in[2];
    AllPtrs P;
    for (int s = 0; s < NBR; s++) {
        int o = 3 + 7 * s;
        P.br[s].cw  = (const float*)d_in[o + 0];
        P.br[s].cb  = (const float*)d_in[o + 1];
        P.br[s].xpw = (const float*)d_in[o + 2];
        P.br[s].dtw = (const float*)d_in[o + 3];
        P.br[s].dtb = (const float*)d_in[o + 4];
        P.br[s].Al  = (const float*)d_in[o + 5];
        P.br[s].Dp  = (const float*)d_in[o + 6];
    }
    float *p_xz, *p_dbc;
    cudaGetSymbolAddress((void**)&p_xz,  g_xz);
    cudaGetSymbolAddress((void**)&p_dbc, g_dbc);

    cudaFuncSetAttribute(in_gemm_staged,  cudaFuncAttributeMaxDynamicSharedMemorySize, 65536);
    cudaFuncSetAttribute(out_gemm_staged, cudaFuncAttributeMaxDynamicSharedMemorySize, 65536);

    flag_kernel<<<NBR, EDI>>>(P);

    // xz = x @ in_w^T : [2052,1024], K=256, split-K(4) staged — 544 blocks
    cudaMemsetAsync(p_xz, 0, (size_t)BLT * ED2 * sizeof(float));
    in_gemm_staged<<<dim3(ED2 / 128, (BLT + 127) / 128, 4), 256, 65536>>>(x, in_w, p_xz);

    // per-branch permuted depthwise conv + SiLU — 1368 blocks
    conv_silu<<<NBR * BB * (LSEQ / CONV_T), 512>>>(P);

    // dBC: batched split-K(8) staged — 544 blocks
    cudaMemsetAsync(p_dbc, 0, (size_t)NBR * BLT * DBCW * sizeof(float));
    dbc_staged<<<dim3(1, (BLT + 127) / 128, NBR * 8), 256>>>(P);

    // chunked selective scan (delta fused) — 288 / 128 / 288 blocks
    scan1<<<NBR * BB * NCHK * 2, 256>>>(P);
    scan2<<<NBR * BB * NS, EDI>>>();
    scan3<<<NBR * BB * NCHK * 2, 256>>>(P);

    // fused combine + out-proj, split-K(8) staged — 272 blocks
    cudaMemsetAsync(d_out, 0, (size_t)BLT * DMO * sizeof(float));
    out_gemm_staged<<<dim3(DMO / 128, (BLT + 127) / 128, 8), 256, 65536>>>(out_w, (float*)d_out);
}

// round 6
// speedup vs baseline: 1.0485x; 1.0485x over previous
#include <cuda_runtime.h>
#include <math.h>
#include <stdint.h>

#define LSEQ 1026
#define BB   2
#define BLT  (BB*LSEQ)   // 2052
#define DMO  256
#define EDI  512
#define ED2  1024
#define NS   16
#define RRW  16
#define DBCW 48
#define NBR  4
#define NCHK 18
#define CLEN 57          // 18*57 = 1026
#define EQ   128

// ------------------------- scratch (device globals; no allocs) -------------
__device__ float g_xz[(size_t)BLT*ED2];
__device__ float g_xa[NBR][(size_t)BLT*EDI];
__device__ float g_dbc[NBR][(size_t)BLT*DBCW];
__device__ float g_sum[(size_t)NBR*BB*NCHK*32*EDI];
__device__ float g_h0[(size_t)NBR*BB*NCHK*NS*EDI];
__device__ float g_g[NBR][(size_t)BLT*EDI];
__device__ int   g_fast[NBR];

struct BranchPtrs { const float *cw,*cb,*xpw,*dtw,*dtb,*Al,*Dp; };
struct AllPtrs { BranchPtrs br[NBR]; };

// ------------------------- index maps ---------------------------------------
__device__ __forceinline__ int pi_map(int p) {
    if (p == 0 || p == LSEQ - 1) return p;
    int q = p - 1;
    int i = q >> 5, j = q & 31;
    return (j << 5) + i + 1;
}
__device__ __forceinline__ int in_row(int s, int p) {
    if (s == 0) return p;
    if (s == 1) return LSEQ - 1 - p;
    if (s == 2) return pi_map(p);
    return pi_map(LSEQ - 1 - p);
}

// store one float4 (col-major transpose) into tile[k][r]
#define ST4(T, K0, R, V) \
    T[(K0)+0][R]=(V).x; T[(K0)+1][R]=(V).y; T[(K0)+2][R]=(V).z; T[(K0)+3][R]=(V).w;

// ====== in-GEMM: xz = x @ in_w^T. 128x128, K=256, 8 pipelined BK=32 stages ==
__global__ __launch_bounds__(256)
void in_gemm_db(const float* __restrict__ A, const float* __restrict__ Bm,
                float* __restrict__ C) {
    extern __shared__ float sh[];
    float (*As)[32][128] = (float(*)[32][128])sh;
    float (*Bs)[32][128] = (float(*)[32][128])(sh + 2 * 32 * 128);
    int tid = threadIdx.x, tx = tid & 15, ty = tid >> 4;
    int n0 = blockIdx.x * 128, m0 = blockIdx.y * 128;
    int r = tid >> 1, kq = (tid & 1) * 16;
    bool mok = (m0 + r) < BLT;
    const float* Ap = A + (size_t)(m0 + r) * DMO + kq;
    const float* Bp = Bm + (size_t)(n0 + r) * DMO + kq;

    float4 a[4], b[4];
#pragma unroll
    for (int i = 0; i < 4; i++) {
        a[i] = mok ? *(const float4*)(Ap + 4 * i) : make_float4(0,0,0,0);
        b[i] = *(const float4*)(Bp + 4 * i);
    }
    float acc[8][8];
#pragma unroll
    for (int i = 0; i < 8; i++)
#pragma unroll
        for (int j = 0; j < 8; j++) acc[i][j] = 0.f;

    const int S = DMO / 32;   // 8
#pragma unroll 1
    for (int s = 0; s < S; s++) {
        int buf = s & 1;
#pragma unroll
        for (int i = 0; i < 4; i++) { ST4(As[buf], kq + 4*i, r, a[i]); }
#pragma unroll
        for (int i = 0; i < 4; i++) { ST4(Bs[buf], kq + 4*i, r, b[i]); }
        __syncthreads();
        if (s + 1 < S) {
            int kb = 32 * (s + 1);
#pragma unroll
            for (int i = 0; i < 4; i++) {
                a[i] = mok ? *(const float4*)(Ap + kb + 4*i) : make_float4(0,0,0,0);
                b[i] = *(const float4*)(Bp + kb + 4*i);
            }
        }
#pragma unroll
        for (int k = 0; k < 32; k++) {
            float4 av0 = *(float4*)&As[buf][k][ty*4];
            float4 av1 = *(float4*)&As[buf][k][64 + ty*4];
            float4 bv0 = *(float4*)&Bs[buf][k][tx*4];
            float4 bv1 = *(float4*)&Bs[buf][k][64 + tx*4];
            float a4[8] = {av0.x,av0.y,av0.z,av0.w, av1.x,av1.y,av1.z,av1.w};
            float b4[8] = {bv0.x,bv0.y,bv0.z,bv0.w, bv1.x,bv1.y,bv1.z,bv1.w};
#pragma unroll
            for (int i = 0; i < 8; i++)
#pragma unroll
                for (int j = 0; j < 8; j++)
                    acc[i][j] = fmaf(a4[i], b4[j], acc[i][j]);
        }
    }
#pragma unroll
    for (int i = 0; i < 8; i++) {
        int m = m0 + (i >> 2) * 64 + ty * 4 + (i & 3);
        if (m >= BLT) continue;
#pragma unroll
        for (int j = 0; j < 8; j++) {
            int n = n0 + (j >> 2) * 64 + tx * 4 + (j & 3);
            C[(size_t)m * ED2 + n] = acc[i][j];
        }
    }
}

// ====== dBC: 128x48, split-K(4), 4 pipelined BK=32 stages, atomic ===========
__global__ __launch_bounds__(256)
void dbc_db(AllPtrs P) {
    __shared__ float As[2][32][128];
    __shared__ float Bs[2][32][48];
    int tid = threadIdx.x, tx = tid & 15, ty = tid >> 4;
    int m0 = blockIdx.y * 128;
    int s = blockIdx.z >> 2, kz = blockIdx.z & 3;
    int kbase = kz * 128;
    const float* A  = g_xa[s];
    const float* Bm = P.br[s].xpw;
    float*       C  = g_dbc[s];

    int r = tid >> 1, kq = (tid & 1) * 16;
    bool mok = (m0 + r) < BLT;
    const float* Ap = A + (size_t)(m0 + r) * EDI + kbase + kq;
    bool bok = tid < 192;
    int br2 = tid >> 2, bkq = (tid & 3) * 8;
    const float* Bp = Bm + (size_t)br2 * EDI + kbase + bkq;

    float4 a[4], b[2];
#pragma unroll
    for (int i = 0; i < 4; i++)
        a[i] = mok ? *(const float4*)(Ap + 4*i) : make_float4(0,0,0,0);
    b[0] = bok ? *(const float4*)Bp : make_float4(0,0,0,0);
    b[1] = bok ? *(const float4*)(Bp + 4) : make_float4(0,0,0,0);

    float acc[8][3];
#pragma unroll
    for (int i = 0; i < 8; i++)
#pragma unroll
        for (int j = 0; j < 3; j++) acc[i][j] = 0.f;

#pragma unroll 1
    for (int st = 0; st < 4; st++) {
        int buf = st & 1;
#pragma unroll
        for (int i = 0; i < 4; i++) { ST4(As[buf], kq + 4*i, r, a[i]); }
        if (bok) { ST4(Bs[buf], bkq, br2, b[0]); ST4(Bs[buf], bkq + 4, br2, b[1]); }
        __syncthreads();
        if (st + 1 < 4) {
            int kb = 32 * (st + 1);
#pragma unroll
            for (int i = 0; i < 4; i++)
                a[i] = mok ? *(const float4*)(Ap + kb + 4*i) : make_float4(0,0,0,0);
            b[0] = bok ? *(const float4*)(Bp + kb) : make_float4(0,0,0,0);
            b[1] = bok ? *(const float4*)(Bp + kb + 4) : make_float4(0,0,0,0);
        }
#pragma unroll
        for (int k = 0; k < 32; k++) {
            float4 av0 = *(float4*)&As[buf][k][ty*4];
            float4 av1 = *(float4*)&As[buf][k][64 + ty*4];
            float a4[8] = {av0.x,av0.y,av0.z,av0.w, av1.x,av1.y,av1.z,av1.w};
            float b4[3] = {Bs[buf][k][tx*3], Bs[buf][k][tx*3+1], Bs[buf][k][tx*3+2]};
#pragma unroll
            for (int i = 0; i < 8; i++)
#pragma unroll
                for (int j = 0; j < 3; j++)
                    acc[i][j] = fmaf(a4[i], b4[j], acc[i][j]);
        }
    }
#pragma unroll
    for (int i = 0; i < 8; i++) {
        int m = m0 + (i >> 2) * 64 + ty * 4 + (i & 3);
        if (m >= BLT) continue;
#pragma unroll
        for (int j = 0; j < 3; j++)
            atomicAdd(&C[(size_t)m * DBCW + tx * 3 + j], acc[i][j]);
    }
}

// ====== out-GEMM + combine gather: 128x128, split-K(4), pipelined ===========
__global__ __launch_bounds__(256)
void out_gemm_db(const float* __restrict__ out_w, float* __restrict__ C) {
    extern __shared__ float sh[];
    float (*As)[32][128] = (float(*)[32][128])sh;
    float (*Bs)[32][128] = (float(*)[32][128])(sh + 2 * 32 * 128);
    int tid = threadIdx.x, tx = tid & 15, ty = tid >> 4;
    int n0 = blockIdx.x * 128, m0 = blockIdx.y * 128;
    int kbase = blockIdx.z * 128;
    int r = tid >> 1, kq = (tid & 1) * 16;
    int m = m0 + r;
    bool mok = m < BLT;
    size_t r0 = 0, r1 = 0, r2 = 0, r3 = 0;
    if (mok) {
        int b = m / LSEQ, l = m % LSEQ;
        r0 = (size_t)m * EDI;
        r1 = (size_t)(b * LSEQ + (LSEQ - 1 - l)) * EDI;
        r2 = (size_t)(b * LSEQ + pi_map(l)) * EDI;
        r3 = (size_t)(b * LSEQ + pi_map(LSEQ - 1 - l)) * EDI;
    }
    const float* Bp = out_w + (size_t)(n0 + r) * EDI + kbase + kq;

    float4 a[4], b[4];
#pragma unroll
    for (int i = 0; i < 4; i++) {
        a[i] = make_float4(0,0,0,0);
        if (mok) {
            int kk = kbase + kq + 4 * i;
            float4 p0 = *(const float4*)(g_g[0]+r0+kk), p1 = *(const float4*)(g_g[1]+r1+kk);
            float4 p2 = *(const float4*)(g_g[2]+r2+kk), p3 = *(const float4*)(g_g[3]+r3+kk);
            a[i].x = 0.25f*(p0.x+p1.x+p2.x+p3.x); a[i].y = 0.25f*(p0.y+p1.y+p2.y+p3.y);
            a[i].z = 0.25f*(p0.z+p1.z+p2.z+p3.z); a[i].w = 0.25f*(p0.w+p1.w+p2.w+p3.w);
        }
        b[i] = *(const float4*)(Bp + 4 * i);
    }
    float acc[8][8];
#pragma unroll
    for (int i = 0; i < 8; i++)
#pragma unroll
        for (int j = 0; j < 8; j++) acc[i][j] = 0.f;

#pragma unroll 1
    for (int st = 0; st < 4; st++) {
        int buf = st & 1;
#pragma unroll
        for (int i = 0; i < 4; i++) { ST4(As[buf], kq + 4*i, r, a[i]); }
#pragma unroll
        for (int i = 0; i < 4; i++) { ST4(Bs[buf], kq + 4*i, r, b[i]); }
        __syncthreads();
        if (st + 1 < 4) {
            int kb = 32 * (st + 1);
#pragma unroll
            for (int i = 0; i < 4; i++) {
                a[i] = make_float4(0,0,0,0);
                if (mok) {
                    int kk = kbase + kb + kq + 4 * i;
                    float4 p0 = *(const float4*)(g_g[0]+r0+kk), p1 = *(const float4*)(g_g[1]+r1+kk);
                    float4 p2 = *(const float4*)(g_g[2]+r2+kk), p3 = *(const float4*)(g_g[3]+r3+kk);
                    a[i].x = 0.25f*(p0.x+p1.x+p2.x+p3.x); a[i].y = 0.25f*(p0.y+p1.y+p2.y+p3.y);
                    a[i].z = 0.25f*(p0.z+p1.z+p2.z+p3.z); a[i].w = 0.25f*(p0.w+p1.w+p2.w+p3.w);
                }
                b[i] = *(const float4*)(Bp + kb + 4 * i);
            }
        }
#pragma unroll
        for (int k = 0; k < 32; k++) {
            float4 av0 = *(float4*)&As[buf][k][ty*4];
            float4 av1 = *(float4*)&As[buf][k][64 + ty*4];
            float4 bv0 = *(float4*)&Bs[buf][k][tx*4];
            float4 bv1 = *(float4*)&Bs[buf][k][64 + tx*4];
            float a4[8] = {av0.x,av0.y,av0.z,av0.w, av1.x,av1.y,av1.z,av1.w};
            float b4[8] = {bv0.x,bv0.y,bv0.z,bv0.w, bv1.x,bv1.y,bv1.z,bv1.w};
#pragma unroll
            for (int i = 0; i < 8; i++)
#pragma unroll
                for (int j = 0; j < 8; j++)
                    acc[i][j] = fmaf(a4[i], b4[j], acc[i][j]);
        }
    }
#pragma unroll
    for (int i = 0; i < 8; i++) {
        int mm = m0 + (i >> 2) * 64 + ty * 4 + (i & 3);
        if (mm >= BLT) continue;
#pragma unroll
        for (int j = 0; j < 8; j++) {
            int n = n0 + (j >> 2) * 64 + tx * 4 + (j & 3);
            atomicAdd(&C[(size_t)mm * DMO + n], acc[i][j]);
        }
    }
}

// ------------------------- structure check for A = -(n+1) -------------------
__global__ void flag_kernel(AllPtrs P) {
    __shared__ int ok;
    int s = blockIdx.x;
    if (threadIdx.x == 0) ok = 1;
    __syncthreads();
    const float* Al = P.br[s].Al;
    int e = threadIdx.x;
    bool good = true;
#pragma unroll
    for (int n = 0; n < NS; n++) {
        float ref = logf((float)(n + 1));
        if (fabsf(Al[e * NS + n] - ref) > 1e-5f * fmaxf(1.f, fabsf(ref))) good = false;
    }
    if (!good) atomicAnd(&ok, 0);
    __syncthreads();
    if (threadIdx.x == 0) g_fast[s] = ok;
}

// ------- depthwise conv (K=4 causal) + SiLU, rolling window over 6 pos ------
#define CONV_T 6
__global__ __launch_bounds__(512)
void conv_silu(AllPtrs P) {
    int blk = blockIdx.x;
    int ntile = LSEQ / CONV_T;           // 171
    int s  = blk / (BB * ntile);
    int rm = blk % (BB * ntile);
    int b  = rm / ntile;
    int l0 = (rm % ntile) * CONV_T;
    int e  = threadIdx.x;
    float4 cwv = *(const float4*)(P.br[s].cw + e * 4);
    float cb = P.br[s].cb[e];
    float v0 = 0.f, v1 = 0.f, v2 = 0.f;
    if (l0 - 3 >= 0) v0 = g_xz[(size_t)(b * LSEQ + in_row(s, l0 - 3)) * ED2 + e];
    if (l0 - 2 >= 0) v1 = g_xz[(size_t)(b * LSEQ + in_row(s, l0 - 2)) * ED2 + e];
    if (l0 - 1 >= 0) v2 = g_xz[(size_t)(b * LSEQ + in_row(s, l0 - 1)) * ED2 + e];
#pragma unroll
    for (int t = 0; t < CONV_T; t++) {
        int l = l0 + t;
        float v3 = g_xz[(size_t)(b * LSEQ + in_row(s, l)) * ED2 + e];
        float acc = cb;
        acc = fmaf(cwv.x, v0, acc);
        acc = fmaf(cwv.y, v1, acc);
        acc = fmaf(cwv.z, v2, acc);
        acc = fmaf(cwv.w, v3, acc);
        float sg = 1.f / (1.f + __expf(-acc));
        g_xa[s][(size_t)(b * LSEQ + l) * EDI + e] = acc * sg;
        v0 = v1; v1 = v2; v2 = v3;
    }
}

// -------- scan phase 1: chunk summaries, delta fused, channel-quarter -------
__global__ __launch_bounds__(128)
void scan1(AllPtrs P) {
    __shared__ float dtw_s[EQ * 17];
    __shared__ float f_s[CLEN][NS];
    __shared__ float Bsm[CLEN * NS];
    int blk = blockIdx.x;
    int quarter = blk & 3;
    int blk2 = blk >> 2;
    int s = blk2 / (BB * NCHK);
    int rem = blk2 % (BB * NCHK);
    int b = rem / NCHK, c = rem % NCHK;
    int e0 = quarter * EQ;
    int e = e0 + threadIdx.x;
    const float* dtw = P.br[s].dtw;
    for (int idx = threadIdx.x; idx < EQ * RRW; idx += blockDim.x)
        dtw_s[(idx >> 4) * 17 + (idx & 15)] = dtw[e0 * RRW + idx];
    for (int idx = threadIdx.x; idx < CLEN * 32; idx += blockDim.x) {
        int t = idx >> 5, q = idx & 31;
        float v = g_dbc[s][(size_t)(b * LSEQ + c * CLEN + t) * DBCW + q];
        if (q < 16) f_s[t][q] = v;
        else        Bsm[t * NS + (q - 16)] = v;
    }
    __syncthreads();
    float w[RRW];
#pragma unroll
    for (int q = 0; q < RRW; q++) w[q] = dtw_s[threadIdx.x * 17 + q];
    float dtb = P.br[s].dtb[e];
    int fast = g_fast[s];
    float A_[NS];
    if (!fast) {
        const float* Al = P.br[s].Al;
#pragma unroll
        for (int n = 0; n < NS; n++) A_[n] = -__expf(Al[e * NS + n]);
    }
    float h[NS], Pn[NS];
#pragma unroll
    for (int n = 0; n < NS; n++) { h[n] = 0.f; Pn[n] = 1.f; }
    float Rp = 1.f;
    const float* xptr = g_xa[s] + (size_t)(b * LSEQ + c * CLEN) * EDI + e;
    float x_cur = xptr[0];
    for (int t = 0; t < CLEN; t++) {
        float x_nxt = (t + 1 < CLEN) ? xptr[(size_t)(t + 1) * EDI] : 0.f;
        float u = dtb;
#pragma unroll
        for (int q = 0; q < RRW; q++) u = fmaf(f_s[t][q], w[q], u);
        float d = fmaxf(u, 0.f) + log1pf(__expf(-fabsf(u)));
        float dx = d * x_cur;
        if (fast) {
            float r = __expf(-d);
            Rp *= r;
            float dA = 1.f;
#pragma unroll
            for (int n = 0; n < NS; n++) {
                dA *= r;
                h[n] = fmaf(dA, h[n], dx * Bsm[t * NS + n]);
            }
        } else {
#pragma unroll
            for (int n = 0; n < NS; n++) {
                float dA = __expf(d * A_[n]);
                Pn[n] *= dA;
                h[n] = fmaf(dA, h[n], dx * Bsm[t * NS + n]);
            }
        }
        x_cur = x_nxt;
    }
    if (fast) {
        float q = 1.f;
#pragma unroll
        for (int n = 0; n < NS; n++) { q *= Rp; Pn[n] = q; }
    }
    size_t base = (size_t)((s * BB + b) * NCHK + c) * 32 * EDI + e;
#pragma unroll
    for (int n = 0; n < NS; n++) g_sum[base + (size_t)n * EDI] = h[n];
#pragma unroll
    for (int n = 0; n < NS; n++) g_sum[base + (size_t)(16 + n) * EDI] = Pn[n];
}

// ---------- scan phase 2: chunk combine, parallel over (s,b,n) --------------
__global__ __launch_bounds__(512)
void scan2() {
    int n = blockIdx.x & 15;
    int sb = blockIdx.x >> 4;          // s*BB+b
    int e = threadIdx.x;
    float h = 0.f;
    for (int c = 0; c < NCHK; c++) {
        size_t idx = (size_t)(sb * NCHK + c);
        g_h0[idx * NS * EDI + (size_t)n * EDI + e] = h;
        size_t pb = idx * 32 * EDI + e;
        float hl = g_sum[pb + (size_t)n * EDI];
        float Pv = g_sum[pb + (size_t)(16 + n) * EDI];
        h = fmaf(Pv, h, hl);
    }
}

// -------- scan phase 3: full walk + gate, delta fused, channel-quarter ------
__global__ __launch_bounds__(128)
void scan3(AllPtrs P) {
    __shared__ float dtw_s[EQ * 17];
    __shared__ float f_s[CLEN][NS];
    __shared__ float Bsm[CLEN * NS];
    __shared__ float Csm[CLEN * NS];
    int blk = blockIdx.x;
    int quarter = blk & 3;
    int blk2 = blk >> 2;
    int s = blk2 / (BB * NCHK);
    int rem = blk2 % (BB * NCHK);
    int b = rem / NCHK, c = rem % NCHK;
    int e0 = quarter * EQ;
    int e = e0 + threadIdx.x;
    const float* dtw = P.br[s].dtw;
    for (int idx = threadIdx.x; idx < EQ * RRW; idx += blockDim.x)
        dtw_s[(idx >> 4) * 17 + (idx & 15)] = dtw[e0 * RRW + idx];
    for (int idx = threadIdx.x; idx < CLEN * DBCW; idx += blockDim.x) {
        int t = idx / DBCW, q = idx % DBCW;
        float v = g_dbc[s][(size_t)(b * LSEQ + c * CLEN + t) * DBCW + q];
        if (q < 16)      f_s[t][q] = v;
        else if (q < 32) Bsm[t * NS + (q - 16)] = v;
        else             Csm[t * NS + (q - 32)] = v;
    }
    __syncthreads();
    float w[RRW];
#pragma unroll
    for (int q = 0; q < RRW; q++) w[q] = dtw_s[threadIdx.x * 17 + q];
    float dtb = P.br[s].dtb[e];
    int fast = g_fast[s];
    float A_[NS];
    if (!fast) {
        const float* Al = P.br[s].Al;
#pragma unroll
        for (int n = 0; n < NS; n++) A_[n] = -__expf(Al[e * NS + n]);
    }
    float Dv = P.br[s].Dp[e];
    float h[NS];
    {
        size_t sb = (size_t)((s * BB + b) * NCHK + c);
        size_t hb = sb * NS * EDI + e;
#pragma unroll
        for (int n = 0; n < NS; n++) h[n] = g_h0[hb + (size_t)n * EDI];
    }
    const float* xptr = g_xa[s] + (size_t)(b * LSEQ + c * CLEN) * EDI + e;
    float x_cur = xptr[0];
    float za_cur = g_xz[(size_t)(b * LSEQ + in_row(s, c * CLEN)) * ED2 + EDI + e];
    for (int t = 0; t < CLEN; t++) {
        int l = c * CLEN + t;
        int bl = b * LSEQ + l;
        float x_nxt = 0.f, za_nxt = 0.f;
        if (t + 1 < CLEN) {
            x_nxt = xptr[(size_t)(t + 1) * EDI];
            za_nxt = g_xz[(size_t)(b * LSEQ + in_row(s, l + 1)) * ED2 + EDI + e];
        }
        float u = dtb;
#pragma unroll
        for (int q = 0; q < RRW; q++) u = fmaf(f_s[t][q], w[q], u);
        float d = fmaxf(u, 0.f) + log1pf(__expf(-fabsf(u)));
        float dx = d * x_cur;
        float acc = Dv * x_cur;
        if (fast) {
            float r = __expf(-d);
            float dA = 1.f;
#pragma unroll
            for (int n = 0; n < NS; n++) {
                dA *= r;
                h[n] = fmaf(dA, h[n], dx * Bsm[t * NS + n]);
                acc = fmaf(h[n], Csm[t * NS + n], acc);
            }
        } else {
#pragma unroll
            for (int n = 0; n < NS; n++) {
                float dA = __expf(d * A_[n]);
                h[n] = fmaf(dA, h[n], dx * Bsm[t * NS + n]);
                acc = fmaf(h[n], Csm[t * NS + n], acc);
            }
        }
        float sz = za_cur / (1.f + __expf(-za_cur));
        g_g[s][(size_t)bl * EDI + e] = acc * sz;
        x_cur = x_nxt; za_cur = za_nxt;
    }
}

// ------------------------- launch ------------------------------------------
extern "C" void kernel_launch(void* const* d_in, const int* in_sizes, int n_in,
                              void* d_out, int out_size) {
    const float* x     = (const float*)d_in[0];
    const float* in_w  = (const float*)d_in[1];
    const float* out_w = (const float*)d_in[2];
    AllPtrs P;
    for (int s = 0; s < NBR; s++) {
        int o = 3 + 7 * s;
        P.br[s].cw  = (const float*)d_in[o + 0];
        P.br[s].cb  = (const float*)d_in[o + 1];
        P.br[s].xpw = (const float*)d_in[o + 2];
        P.br[s].dtw = (const float*)d_in[o + 3];
        P.br[s].dtb = (const float*)d_in[o + 4];
        P.br[s].Al  = (const float*)d_in[o + 5];
        P.br[s].Dp  = (const float*)d_in[o + 6];
    }
    float *p_xz, *p_dbc;
    cudaGetSymbolAddress((void**)&p_xz,  g_xz);
    cudaGetSymbolAddress((void**)&p_dbc, g_dbc);

    cudaFuncSetAttribute(in_gemm_db,  cudaFuncAttributeMaxDynamicSharedMemorySize, 65536);
    cudaFuncSetAttribute(out_gemm_db, cudaFuncAttributeMaxDynamicSharedMemorySize, 65536);

    flag_kernel<<<NBR, EDI>>>(P);

    // xz = x @ in_w^T : [2052,1024], K=256, no split-K, pipelined — 128 blocks
    in_gemm_db<<<dim3(ED2 / 128, (BLT + 127) / 128), 256, 65536>>>(x, in_w, p_xz);

    // per-branch permuted depthwise conv + SiLU — 1368 blocks
    conv_silu<<<NBR * BB * (LSEQ / CONV_T), 512>>>(P);

    // dBC: batched split-K(4) pipelined — 272 blocks
    cudaMemsetAsync(p_dbc, 0, (size_t)NBR * BLT * DBCW * sizeof(float));
    dbc_db<<<dim3(1, (BLT + 127) / 128, NBR * 4), 256>>>(P);

    // chunked selective scan (delta fused, channel-quartered) — 576/128/576
    scan1<<<NBR * BB * NCHK * 4, 128>>>(P);
    scan2<<<NBR * BB * NS, EDI>>>();
    scan3<<<NBR * BB * NCHK * 4, 128>>>(P);

    // fused combine + out-proj, split-K(4) pipelined — 136 blocks
    cudaMemsetAsync(d_out, 0, (size_t)BLT * DMO * sizeof(float));
    out_gemm_db<<<dim3(DMO / 128, (BLT + 127) / 128, 4), 256, 65536>>>(out_w, (float*)d_out);
}

// round 7
// speedup vs baseline: 1.1972x; 1.1418x over previous
#include <cuda_runtime.h>
#include <math.h>
#include <stdint.h>

#define LSEQ 1026
#define BB   2
#define BLT  (BB*LSEQ)   // 2052
#define DMO  256
#define EDI  512
#define ED2  1024
#define NS   16
#define RRW  16
#define DBCW 48
#define NBR  4
#define NCHK 18
#define CLEN 57          // 18*57 = 1026
#define EQ   128

// ------------------------- scratch (device globals; no allocs) -------------
__device__ float g_xz[(size_t)BLT*ED2];
__device__ float g_xa[NBR][(size_t)BLT*EDI];
__device__ float g_dbc[NBR][(size_t)BLT*DBCW];
__device__ float g_sum[(size_t)NBR*BB*NCHK*32*EDI];
__device__ float g_h0[(size_t)NBR*BB*NCHK*NS*EDI];
__device__ float g_g[NBR][(size_t)BLT*EDI];
__device__ int   g_fast[NBR];

struct BranchPtrs { const float *cw,*cb,*xpw,*dtw,*dtb,*Al,*Dp; };
struct AllPtrs { BranchPtrs br[NBR]; };

// ------------------------- index maps ---------------------------------------
__device__ __forceinline__ int pi_map(int p) {
    if (p == 0 || p == LSEQ - 1) return p;
    int q = p - 1;
    int i = q >> 5, j = q & 31;
    return (j << 5) + i + 1;
}
__device__ __forceinline__ int in_row(int s, int p) {
    if (s == 0) return p;
    if (s == 1) return LSEQ - 1 - p;
    if (s == 2) return pi_map(p);
    return pi_map(LSEQ - 1 - p);
}

// ------------------------- tf32 mma helpers ---------------------------------
__device__ __forceinline__ float to_tf32(float x) {
    uint32_t u; asm("cvt.rna.tf32.f32 %0, %1;" : "=r"(u) : "f"(x));
    return __uint_as_float(u);
}
__device__ __forceinline__ void mma_tf32(float c[4], const uint32_t a[4],
                                         uint32_t b0, uint32_t b1) {
    asm volatile("mma.sync.aligned.m16n8k8.row.col.f32.tf32.tf32.f32 "
        "{%0,%1,%2,%3}, {%4,%5,%6,%7}, {%8,%9}, {%0,%1,%2,%3};"
        : "+f"(c[0]), "+f"(c[1]), "+f"(c[2]), "+f"(c[3])
        : "r"(a[0]), "r"(a[1]), "r"(a[2]), "r"(a[3]), "r"(b0), "r"(b1));
}
#define ST4C(T, K0, R, V) \
    T[(K0)+0][R]=to_tf32((V).x); T[(K0)+1][R]=to_tf32((V).y); \
    T[(K0)+2][R]=to_tf32((V).z); T[(K0)+3][R]=to_tf32((V).w);

// ====== in-GEMM (tf32 mma): xz = x @ in_w^T. 128x64 tile, K=256 ============
// 256 thr, 8 warps (4m x 2n), warp-tile 32x32. grid (16, 17) = 272 blocks.
__global__ __launch_bounds__(256)
void in_gemm_mma(const float* __restrict__ A, const float* __restrict__ Bm,
                 float* __restrict__ C) {
    extern __shared__ float sh[];
    float (*As)[32][136] = (float(*)[32][136])sh;
    float (*Bs)[32][72]  = (float(*)[32][72])(sh + 2*32*136);
    int tid = threadIdx.x;
    int n0 = blockIdx.x * 64, m0 = blockIdx.y * 128;
    int ra = tid >> 1, ka = (tid & 1) * 16;
    bool mok = (m0 + ra) < BLT;
    const float* Ap = A + (size_t)(m0 + ra) * DMO + ka;
    int rb = tid >> 2, kb = (tid & 3) * 8;
    const float* Bp = Bm + (size_t)(n0 + rb) * DMO + kb;
    int lane = tid & 31, wid = tid >> 5;
    int g = lane >> 2, t4 = lane & 3;
    int wm = (wid & 3) * 32, wn = (wid >> 2) * 32;

    float4 a[4], b[2];
#pragma unroll
    for (int i = 0; i < 4; i++)
        a[i] = mok ? *(const float4*)(Ap + 4*i) : make_float4(0,0,0,0);
    b[0] = *(const float4*)Bp; b[1] = *(const float4*)(Bp + 4);

    float acc[2][4][4];
#pragma unroll
    for (int mi = 0; mi < 2; mi++)
#pragma unroll
        for (int ni = 0; ni < 4; ni++)
#pragma unroll
            for (int q = 0; q < 4; q++) acc[mi][ni][q] = 0.f;

#pragma unroll 1
    for (int s = 0; s < 8; s++) {
        int buf = s & 1;
#pragma unroll
        for (int i = 0; i < 4; i++) { ST4C(As[buf], ka + 4*i, ra, a[i]); }
        ST4C(Bs[buf], kb, rb, b[0]); ST4C(Bs[buf], kb + 4, rb, b[1]);
        __syncthreads();
        if (s + 1 < 8) {
            int off = 32 * (s + 1);
#pragma unroll
            for (int i = 0; i < 4; i++)
                a[i] = mok ? *(const float4*)(Ap + off + 4*i) : make_float4(0,0,0,0);
            b[0] = *(const float4*)(Bp + off); b[1] = *(const float4*)(Bp + off + 4);
        }
#pragma unroll
        for (int k8 = 0; k8 < 4; k8++) {
            int kr = k8 * 8 + t4;
            uint32_t af[2][4];
#pragma unroll
            for (int mi = 0; mi < 2; mi++) {
                int mb = wm + mi * 16 + g;
                af[mi][0] = __float_as_uint(As[buf][kr][mb]);
                af[mi][1] = __float_as_uint(As[buf][kr][mb + 8]);
                af[mi][2] = __float_as_uint(As[buf][kr + 4][mb]);
                af[mi][3] = __float_as_uint(As[buf][kr + 4][mb + 8]);
            }
#pragma unroll
            for (int ni = 0; ni < 4; ni++) {
                int nb = wn + ni * 8 + g;
                uint32_t b0 = __float_as_uint(Bs[buf][kr][nb]);
                uint32_t b1 = __float_as_uint(Bs[buf][kr + 4][nb]);
                mma_tf32(acc[0][ni], af[0], b0, b1);
                mma_tf32(acc[1][ni], af[1], b0, b1);
            }
        }
        __syncthreads();
    }
#pragma unroll
    for (int mi = 0; mi < 2; mi++)
#pragma unroll
        for (int ni = 0; ni < 4; ni++) {
            int row = m0 + wm + mi * 16 + g;
            int col = n0 + wn + ni * 8 + 2 * t4;
            if (row < BLT)
                *(float2*)&C[(size_t)row * ED2 + col] =
                    make_float2(acc[mi][ni][0], acc[mi][ni][1]);
            if (row + 8 < BLT)
                *(float2*)&C[(size_t)(row + 8) * ED2 + col] =
                    make_float2(acc[mi][ni][2], acc[mi][ni][3]);
        }
}

// ====== dBC (tf32 mma): 64x48 tile, K=512, grid (4, 33) = 132 blocks ========
// 128 thr, 4 warps (2m x 2n), warp-tile 32x24.
__global__ __launch_bounds__(128)
void dbc_mma(AllPtrs P) {
    __shared__ float As[2][32][72];
    __shared__ float Bs[2][32][56];
    int tid = threadIdx.x;
    int s = blockIdx.x;
    int m0 = blockIdx.y * 64;
    const float* A  = g_xa[s];
    const float* Bm = P.br[s].xpw;
    float*       C  = g_dbc[s];
    int ra = tid >> 1, ka = (tid & 1) * 16;
    bool mok = (m0 + ra) < BLT;
    const float* Ap = A + (size_t)(m0 + ra) * EDI + ka;
    bool bok = tid < 96;
    int rb = tid >> 1;                   // 0..47 when bok
    const float* Bp = Bm + (size_t)rb * EDI + ka;
    int lane = tid & 31, wid = tid >> 5;
    int g = lane >> 2, t4 = lane & 3;
    int wm = (wid & 1) * 32, wn = (wid >> 1) * 24;

    float4 a[4], b[4];
#pragma unroll
    for (int i = 0; i < 4; i++) {
        a[i] = mok ? *(const float4*)(Ap + 4*i) : make_float4(0,0,0,0);
        b[i] = bok ? *(const float4*)(Bp + 4*i) : make_float4(0,0,0,0);
    }
    float acc[2][3][4];
#pragma unroll
    for (int mi = 0; mi < 2; mi++)
#pragma unroll
        for (int ni = 0; ni < 3; ni++)
#pragma unroll
            for (int q = 0; q < 4; q++) acc[mi][ni][q] = 0.f;

#pragma unroll 1
    for (int s2 = 0; s2 < 16; s2++) {
        int buf = s2 & 1;
#pragma unroll
        for (int i = 0; i < 4; i++) { ST4C(As[buf], ka + 4*i, ra, a[i]); }
        if (bok) {
#pragma unroll
            for (int i = 0; i < 4; i++) { ST4C(Bs[buf], ka + 4*i, rb, b[i]); }
        }
        __syncthreads();
        if (s2 + 1 < 16) {
            int off = 32 * (s2 + 1);
#pragma unroll
            for (int i = 0; i < 4; i++) {
                a[i] = mok ? *(const float4*)(Ap + off + 4*i) : make_float4(0,0,0,0);
                b[i] = bok ? *(const float4*)(Bp + off + 4*i) : make_float4(0,0,0,0);
            }
        }
#pragma unroll
        for (int k8 = 0; k8 < 4; k8++) {
            int kr = k8 * 8 + t4;
            uint32_t af[2][4];
#pragma unroll
            for (int mi = 0; mi < 2; mi++) {
                int mb = wm + mi * 16 + g;
                af[mi][0] = __float_as_uint(As[buf][kr][mb]);
                af[mi][1] = __float_as_uint(As[buf][kr][mb + 8]);
                af[mi][2] = __float_as_uint(As[buf][kr + 4][mb]);
                af[mi][3] = __float_as_uint(As[buf][kr + 4][mb + 8]);
            }
#pragma unroll
            for (int ni = 0; ni < 3; ni++) {
                int nb = wn + ni * 8 + g;
                uint32_t b0 = __float_as_uint(Bs[buf][kr][nb]);
                uint32_t b1 = __float_as_uint(Bs[buf][kr + 4][nb]);
                mma_tf32(acc[0][ni], af[0], b0, b1);
                mma_tf32(acc[1][ni], af[1], b0, b1);
            }
        }
        __syncthreads();
    }
#pragma unroll
    for (int mi = 0; mi < 2; mi++)
#pragma unroll
        for (int ni = 0; ni < 3; ni++) {
            int row = m0 + wm + mi * 16 + g;
            int col = wn + ni * 8 + 2 * t4;
            if (row < BLT)
                *(float2*)&C[(size_t)row * DBCW + col] =
                    make_float2(acc[mi][ni][0], acc[mi][ni][1]);
            if (row + 8 < BLT)
                *(float2*)&C[(size_t)(row + 8) * DBCW + col] =
                    make_float2(acc[mi][ni][2], acc[mi][ni][3]);
        }
}

// ====== out-GEMM (tf32 mma) + combine gather: 64x64, K=512, grid (4,33) =====
// 128 thr, 4 warps (2m x 2n), warp-tile 32x32. Direct store to d_out.
__global__ __launch_bounds__(128)
void out_gemm_mma(const float* __restrict__ out_w, float* __restrict__ C) {
    __shared__ float As[2][32][72];
    __shared__ float Bs[2][32][72];
    int tid = threadIdx.x;
    int n0 = blockIdx.x * 64, m0 = blockIdx.y * 64;
    int ra = tid >> 1, ka = (tid & 1) * 16;
    int m = m0 + ra;
    bool mok = m < BLT;
    size_t r0 = 0, r1 = 0, r2 = 0, r3 = 0;
    if (mok) {
        int b = m / LSEQ, l = m % LSEQ;
        r0 = (size_t)m * EDI;
        r1 = (size_t)(b * LSEQ + (LSEQ - 1 - l)) * EDI;
        r2 = (size_t)(b * LSEQ + pi_map(l)) * EDI;
        r3 = (size_t)(b * LSEQ + pi_map(LSEQ - 1 - l)) * EDI;
    }
    const float* Bp = out_w + (size_t)(n0 + ra) * EDI + ka;
    int lane = tid & 31, wid = tid >> 5;
    int g = lane >> 2, t4 = lane & 3;
    int wm = (wid & 1) * 32, wn = (wid >> 1) * 32;

    float4 a[4], b[4];
#pragma unroll
    for (int i = 0; i < 4; i++) {
        a[i] = make_float4(0,0,0,0);
        if (mok) {
            int kk = ka + 4 * i;
            float4 p0 = *(const float4*)(g_g[0]+r0+kk), p1 = *(const float4*)(g_g[1]+r1+kk);
            float4 p2 = *(const float4*)(g_g[2]+r2+kk), p3 = *(const float4*)(g_g[3]+r3+kk);
            a[i].x = 0.25f*(p0.x+p1.x+p2.x+p3.x); a[i].y = 0.25f*(p0.y+p1.y+p2.y+p3.y);
            a[i].z = 0.25f*(p0.z+p1.z+p2.z+p3.z); a[i].w = 0.25f*(p0.w+p1.w+p2.w+p3.w);
        }
        b[i] = *(const float4*)(Bp + 4 * i);
    }
    float acc[2][4][4];
#pragma unroll
    for (int mi = 0; mi < 2; mi++)
#pragma unroll
        for (int ni = 0; ni < 4; ni++)
#pragma unroll
            for (int q = 0; q < 4; q++) acc[mi][ni][q] = 0.f;

#pragma unroll 1
    for (int s2 = 0; s2 < 16; s2++) {
        int buf = s2 & 1;
#pragma unroll
        for (int i = 0; i < 4; i++) { ST4C(As[buf], ka + 4*i, ra, a[i]); }
#pragma unroll
        for (int i = 0; i < 4; i++) { ST4C(Bs[buf], ka + 4*i, ra, b[i]); }
        __syncthreads();
        if (s2 + 1 < 16) {
            int off = 32 * (s2 + 1);
#pragma unroll
            for (int i = 0; i < 4; i++) {
                a[i] = make_float4(0,0,0,0);
                if (mok) {
                    int kk = off + ka + 4 * i;
                    float4 p0 = *(const float4*)(g_g[0]+r0+kk), p1 = *(const float4*)(g_g[1]+r1+kk);
                    float4 p2 = *(const float4*)(g_g[2]+r2+kk), p3 = *(const float4*)(g_g[3]+r3+kk);
                    a[i].x = 0.25f*(p0.x+p1.x+p2.x+p3.x); a[i].y = 0.25f*(p0.y+p1.y+p2.y+p3.y);
                    a[i].z = 0.25f*(p0.z+p1.z+p2.z+p3.z); a[i].w = 0.25f*(p0.w+p1.w+p2.w+p3.w);
                }
                b[i] = *(const float4*)(Bp + off + 4 * i);
            }
        }
#pragma unroll
        for (int k8 = 0; k8 < 4; k8++) {
            int kr = k8 * 8 + t4;
            uint32_t af[2][4];
#pragma unroll
            for (int mi = 0; mi < 2; mi++) {
                int mb = wm + mi * 16 + g;
                af[mi][0] = __float_as_uint(As[buf][kr][mb]);
                af[mi][1] = __float_as_uint(As[buf][kr][mb + 8]);
                af[mi][2] = __float_as_uint(As[buf][kr + 4][mb]);
                af[mi][3] = __float_as_uint(As[buf][kr + 4][mb + 8]);
            }
#pragma unroll
            for (int ni = 0; ni < 4; ni++) {
                int nb = wn + ni * 8 + g;
                uint32_t b0 = __float_as_uint(Bs[buf][kr][nb]);
                uint32_t b1 = __float_as_uint(Bs[buf][kr + 4][nb]);
                mma_tf32(acc[0][ni], af[0], b0, b1);
                mma_tf32(acc[1][ni], af[1], b0, b1);
            }
        }
        __syncthreads();
    }
#pragma unroll
    for (int mi = 0; mi < 2; mi++)
#pragma unroll
        for (int ni = 0; ni < 4; ni++) {
            int row = m0 + wm + mi * 16 + g;
            int col = n0 + wn + ni * 8 + 2 * t4;
            if (row < BLT)
                *(float2*)&C[(size_t)row * DMO + col] =
                    make_float2(acc[mi][ni][0], acc[mi][ni][1]);
            if (row + 8 < BLT)
                *(float2*)&C[(size_t)(row + 8) * DMO + col] =
                    make_float2(acc[mi][ni][2], acc[mi][ni][3]);
        }
}

// ------------------------- structure check for A = -(n+1) -------------------
__global__ void flag_kernel(AllPtrs P) {
    __shared__ int ok;
    int s = blockIdx.x;
    if (threadIdx.x == 0) ok = 1;
    __syncthreads();
    const float* Al = P.br[s].Al;
    int e = threadIdx.x;
    bool good = true;
#pragma unroll
    for (int n = 0; n < NS; n++) {
        float ref = logf((float)(n + 1));
        if (fabsf(Al[e * NS + n] - ref) > 1e-5f * fmaxf(1.f, fabsf(ref))) good = false;
    }
    if (!good) atomicAnd(&ok, 0);
    __syncthreads();
    if (threadIdx.x == 0) g_fast[s] = ok;
}

// ------- depthwise conv (K=4 causal) + SiLU, rolling window over 6 pos ------
#define CONV_T 6
__global__ __launch_bounds__(512)
void conv_silu(AllPtrs P) {
    int blk = blockIdx.x;
    int ntile = LSEQ / CONV_T;           // 171
    int s  = blk / (BB * ntile);
    int rm = blk % (BB * ntile);
    int b  = rm / ntile;
    int l0 = (rm % ntile) * CONV_T;
    int e  = threadIdx.x;
    float4 cwv = *(const float4*)(P.br[s].cw + e * 4);
    float cb = P.br[s].cb[e];
    float v0 = 0.f, v1 = 0.f, v2 = 0.f;
    if (l0 - 3 >= 0) v0 = g_xz[(size_t)(b * LSEQ + in_row(s, l0 - 3)) * ED2 + e];
    if (l0 - 2 >= 0) v1 = g_xz[(size_t)(b * LSEQ + in_row(s, l0 - 2)) * ED2 + e];
    if (l0 - 1 >= 0) v2 = g_xz[(size_t)(b * LSEQ + in_row(s, l0 - 1)) * ED2 + e];
#pragma unroll
    for (int t = 0; t < CONV_T; t++) {
        int l = l0 + t;
        float v3 = g_xz[(size_t)(b * LSEQ + in_row(s, l)) * ED2 + e];
        float acc = cb;
        acc = fmaf(cwv.x, v0, acc);
        acc = fmaf(cwv.y, v1, acc);
        acc = fmaf(cwv.z, v2, acc);
        acc = fmaf(cwv.w, v3, acc);
        float sg = 1.f / (1.f + __expf(-acc));
        g_xa[s][(size_t)(b * LSEQ + l) * EDI + e] = acc * sg;
        v0 = v1; v1 = v2; v2 = v3;
    }
}

// -------- scan phase 1: chunk summaries, delta fused, channel-quarter -------
__global__ __launch_bounds__(128)
void scan1(AllPtrs P) {
    __shared__ float dtw_s[EQ * 17];
    __shared__ float f_s[CLEN][NS];
    __shared__ float Bsm[CLEN * NS];
    int blk = blockIdx.x;
    int quarter = blk & 3;
    int blk2 = blk >> 2;
    int s = blk2 / (BB * NCHK);
    int rem = blk2 % (BB * NCHK);
    int b = rem / NCHK, c = rem % NCHK;
    int e0 = quarter * EQ;
    int e = e0 + threadIdx.x;
    const float* dtw = P.br[s].dtw;
    for (int idx = threadIdx.x; idx < EQ * RRW; idx += blockDim.x)
        dtw_s[(idx >> 4) * 17 + (idx & 15)] = dtw[e0 * RRW + idx];
    for (int idx = threadIdx.x; idx < CLEN * 32; idx += blockDim.x) {
        int t = idx >> 5, q = idx & 31;
        float v = g_dbc[s][(size_t)(b * LSEQ + c * CLEN + t) * DBCW + q];
        if (q < 16) f_s[t][q] = v;
        else        Bsm[t * NS + (q - 16)] = v;
    }
    __syncthreads();
    float w[RRW];
#pragma unroll
    for (int q = 0; q < RRW; q++) w[q] = dtw_s[threadIdx.x * 17 + q];
    float dtb = P.br[s].dtb[e];
    int fast = g_fast[s];
    float A_[NS];
    if (!fast) {
        const float* Al = P.br[s].Al;
#pragma unroll
        for (int n = 0; n < NS; n++) A_[n] = -__expf(Al[e * NS + n]);
    }
    float h[NS], Pn[NS];
#pragma unroll
    for (int n = 0; n < NS; n++) { h[n] = 0.f; Pn[n] = 1.f; }
    float Rp = 1.f;
    const float* xptr = g_xa[s] + (size_t)(b * LSEQ + c * CLEN) * EDI + e;
    float x_cur = xptr[0];
    for (int t = 0; t < CLEN; t++) {
        float x_nxt = (t + 1 < CLEN) ? xptr[(size_t)(t + 1) * EDI] : 0.f;
        float u = dtb;
#pragma unroll
        for (int q = 0; q < RRW; q++) u = fmaf(f_s[t][q], w[q], u);
        float d = fmaxf(u, 0.f) + log1pf(__expf(-fabsf(u)));
        float dx = d * x_cur;
        if (fast) {
            float r = __expf(-d);
            Rp *= r;
            float dA = 1.f;
#pragma unroll
            for (int n = 0; n < NS; n++) {
                dA *= r;
                h[n] = fmaf(dA, h[n], dx * Bsm[t * NS + n]);
            }
        } else {
#pragma unroll
            for (int n = 0; n < NS; n++) {
                float dA = __expf(d * A_[n]);
                Pn[n] *= dA;
                h[n] = fmaf(dA, h[n], dx * Bsm[t * NS + n]);
            }
        }
        x_cur = x_nxt;
    }
    if (fast) {
        float q = 1.f;
#pragma unroll
        for (int n = 0; n < NS; n++) { q *= Rp; Pn[n] = q; }
    }
    size_t base = (size_t)((s * BB + b) * NCHK + c) * 32 * EDI + e;
#pragma unroll
    for (int n = 0; n < NS; n++) g_sum[base + (size_t)n * EDI] = h[n];
#pragma unroll
    for (int n = 0; n < NS; n++) g_sum[base + (size_t)(16 + n) * EDI] = Pn[n];
}

// ---------- scan phase 2: chunk combine, parallel over (s,b,n) --------------
__global__ __launch_bounds__(512)
void scan2() {
    int n = blockIdx.x & 15;
    int sb = blockIdx.x >> 4;          // s*BB+b
    int e = threadIdx.x;
    float h = 0.f;
    for (int c = 0; c < NCHK; c++) {
        size_t idx = (size_t)(sb * NCHK + c);
        g_h0[idx * NS * EDI + (size_t)n * EDI + e] = h;
        size_t pb = idx * 32 * EDI + e;
        float hl = g_sum[pb + (size_t)n * EDI];
        float Pv = g_sum[pb + (size_t)(16 + n) * EDI];
        h = fmaf(Pv, h, hl);
    }
}

// -------- scan phase 3: full walk + gate, delta fused, channel-quarter ------
__global__ __launch_bounds__(128)
void scan3(AllPtrs P) {
    __shared__ float dtw_s[EQ * 17];
    __shared__ float f_s[CLEN][NS];
    __shared__ float Bsm[CLEN * NS];
    __shared__ float Csm[CLEN * NS];
    int blk = blockIdx.x;
    int quarter = blk & 3;
    int blk2 = blk >> 2;
    int s = blk2 / (BB * NCHK);
    int rem = blk2 % (BB * NCHK);
    int b = rem / NCHK, c = rem % NCHK;
    int e0 = quarter * EQ;
    int e = e0 + threadIdx.x;
    const float* dtw = P.br[s].dtw;
    for (int idx = threadIdx.x; idx < EQ * RRW; idx += blockDim.x)
        dtw_s[(idx >> 4) * 17 + (idx & 15)] = dtw[e0 * RRW + idx];
    for (int idx = threadIdx.x; idx < CLEN * DBCW; idx += blockDim.x) {
        int t = idx / DBCW, q = idx % DBCW;
        float v = g_dbc[s][(size_t)(b * LSEQ + c * CLEN + t) * DBCW + q];
        if (q < 16)      f_s[t][q] = v;
        else if (q < 32) Bsm[t * NS + (q - 16)] = v;
        else             Csm[t * NS + (q - 32)] = v;
    }
    __syncthreads();
    float w[RRW];
#pragma unroll
    for (int q = 0; q < RRW; q++) w[q] = dtw_s[threadIdx.x * 17 + q];
    float dtb = P.br[s].dtb[e];
    int fast = g_fast[s];
    float A_[NS];
    if (!fast) {
        const float* Al = P.br[s].Al;
#pragma unroll
        for (int n = 0; n < NS; n++) A_[n] = -__expf(Al[e * NS + n]);
    }
    float Dv = P.br[s].Dp[e];
    float h[NS];
    {
        size_t sb = (size_t)((s * BB + b) * NCHK + c);
        size_t hb = sb * NS * EDI + e;
#pragma unroll
        for (int n = 0; n < NS; n++) h[n] = g_h0[hb + (size_t)n * EDI];
    }
    const float* xptr = g_xa[s] + (size_t)(b * LSEQ + c * CLEN) * EDI + e;
    float x_cur = xptr[0];
    float za_cur = g_xz[(size_t)(b * LSEQ + in_row(s, c * CLEN)) * ED2 + EDI + e];
    for (int t = 0; t < CLEN; t++) {
        int l = c * CLEN + t;
        int bl = b * LSEQ + l;
        float x_nxt = 0.f, za_nxt = 0.f;
        if (t + 1 < CLEN) {
            x_nxt = xptr[(size_t)(t + 1) * EDI];
            za_nxt = g_xz[(size_t)(b * LSEQ + in_row(s, l + 1)) * ED2 + EDI + e];
        }
        float u = dtb;
#pragma unroll
        for (int q = 0; q < RRW; q++) u = fmaf(f_s[t][q], w[q], u);
        float d = fmaxf(u, 0.f) + log1pf(__expf(-fabsf(u)));
        float dx = d * x_cur;
        float acc = Dv * x_cur;
        if (fast) {
            float r = __expf(-d);
            float dA = 1.f;
#pragma unroll
            for (int n = 0; n < NS; n++) {
                dA *= r;
                h[n] = fmaf(dA, h[n], dx * Bsm[t * NS + n]);
                acc = fmaf(h[n], Csm[t * NS + n], acc);
            }
        } else {
#pragma unroll
            for (int n = 0; n < NS; n++) {
                float dA = __expf(d * A_[n]);
                h[n] = fmaf(dA, h[n], dx * Bsm[t * NS + n]);
                acc = fmaf(h[n], Csm[t * NS + n], acc);
            }
        }
        float sz = za_cur / (1.f + __expf(-za_cur));
        g_g[s][(size_t)bl * EDI + e] = acc * sz;
        x_cur = x_nxt; za_cur = za_nxt;
    }
}

// ------------------------- launch ------------------------------------------
extern "C" void kernel_launch(void* const* d_in, const int* in_sizes, int n_in,
                              void* d_out, int out_size) {
    const float* x     = (const float*)d_in[0];
    const float* in_w  = (const float*)d_in[1];
    const float* out_w = (const float*)d_in[2];
    AllPtrs P;
    for (int s = 0; s < NBR; s++) {
        int o = 3 + 7 * s;
        P.br[s].cw  = (const float*)d_in[o + 0];
        P.br[s].cb  = (const float*)d_in[o + 1];
        P.br[s].xpw = (const float*)d_in[o + 2];
        P.br[s].dtw = (const float*)d_in[o + 3];
        P.br[s].dtb = (const float*)d_in[o + 4];
        P.br[s].Al  = (const float*)d_in[o + 5];
        P.br[s].Dp  = (const float*)d_in[o + 6];
    }
    float* p_xz;
    cudaGetSymbolAddress((void**)&p_xz, g_xz);

    const int IN_SMEM = (2*32*136 + 2*32*72) * 4;  // 53248 bytes
    cudaFuncSetAttribute(in_gemm_mma, cudaFuncAttributeMaxDynamicSharedMemorySize, IN_SMEM);

    flag_kernel<<<NBR, EDI>>>(P);

    // xz = x @ in_w^T : [2052,1024], K=256 — tf32 mma, 272 blocks
    in_gemm_mma<<<dim3(ED2 / 64, (BLT + 127) / 128), 256, IN_SMEM>>>(x, in_w, p_xz);

    // per-branch permuted depthwise conv + SiLU — 1368 blocks
    conv_silu<<<NBR * BB * (LSEQ / CONV_T), 512>>>(P);

    // dBC = xa @ xp_w^T : [2052,48], K=512 — tf32 mma, 132 blocks
    dbc_mma<<<dim3(NBR, (BLT + 63) / 64), 128>>>(P);

    // chunked selective scan (delta fused, channel-quartered) — 576/128/576
    scan1<<<NBR * BB * NCHK * 4, 128>>>(P);
    scan2<<<NBR * BB * NS, EDI>>>();
    scan3<<<NBR * BB * NCHK * 4, 128>>>(P);

    // fused combine + out-proj : [2052,256], K=512 — tf32 mma, 132 blocks
    out_gemm_mma<<<dim3(DMO / 64, (BLT + 63) / 64), 128>>>(out_w, (float*)d_out);
}